// round 1
// baseline (speedup 1.0000x reference)
#include <cuda_runtime.h>
#include <math.h>

#define NWIN 2048
#define NT   66
#define C    256
#define NH   8
#define HD   32
#define TOKN 2
#define QK_SCALE 0.17677669529663687f   // 1/sqrt(32)

// shared memory layout (floats)
#define XS_STRIDE 260
#define QS_STRIDE 33
#define SS_STRIDE 67
#define WS_STRIDE 65

#define XS_OFF 0
#define OS_OFF (XS_OFF + NT*XS_STRIDE)          // 17160
#define WS_OFF (OS_OFF + NT*XS_STRIDE)          // 34320
#define QS_OFF (WS_OFF + 96*WS_STRIDE)          // 40560
#define KS_OFF (QS_OFF + NT*QS_STRIDE)          // 42738
#define VS_OFF (KS_OFF + NT*QS_STRIDE)          // 44916
#define SS_OFF (VS_OFF + NT*QS_STRIDE)          // 47094
#define SM_TOTAL (SS_OFF + NT*SS_STRIDE)        // 51516 floats = 206064 B

// Tiled GEMM: out[r][c] += sum_k xsrc[r][k] * Wg[grow(c)][k]
// 16x16 thread grid: thread owns up to 5 rows (rg+16i) x 6 cols (cg*6+j).
// mode 0: QKV slice for head h  -> grow = (c/32)*256 + h*32 + (c%32)
// mode 1: proj tile             -> grow = colbase + c   (guarded < 256)
__device__ __forceinline__ void gemm_tile(
    float* sm, int xoff, const float* __restrict__ Wg,
    int mode, int h, int colbase, int tid, float acc[5][6])
{
    const int cg = tid & 15;
    const int rg = tid >> 4;
    int roff[5];
#pragma unroll
    for (int i = 0; i < 5; i++) roff[i] = xoff + (rg + 16*i)*XS_STRIDE;

    for (int k0 = 0; k0 < C; k0 += 64) {
        __syncthreads();
        // stage W chunk [96 cols][64 k] into smem (float4 global reads)
        for (int idx = tid; idx < 96*16; idx += 256) {
            int c  = idx >> 4;
            int k4 = (idx & 15) * 4;
            int grow;
            if (mode == 0) grow = ((c >> 5) << 8) + (h << 5) + (c & 31);
            else           grow = colbase + c;
            if (mode == 0 || grow < C) {
                float4 w4 = *(const float4*)(Wg + (size_t)grow*C + k0 + k4);
                float* d = &sm[WS_OFF + c*WS_STRIDE + k4];
                d[0] = w4.x; d[1] = w4.y; d[2] = w4.z; d[3] = w4.w;
            }
        }
        __syncthreads();
        // accumulate
        const float* wsb = &sm[WS_OFF + (cg*6)*WS_STRIDE];
#pragma unroll 4
        for (int kk = 0; kk < 64; kk += 4) {
            float4 xv[5];
#pragma unroll
            for (int i = 0; i < 5; i++)
                xv[i] = *(const float4*)&sm[roff[i] + k0 + kk];
#pragma unroll
            for (int j = 0; j < 6; j++) {
                const float* wp = wsb + j*WS_STRIDE + kk;
                float w0 = wp[0], w1 = wp[1], w2 = wp[2], w3 = wp[3];
#pragma unroll
                for (int i = 0; i < 5; i++) {
                    acc[i][j] += xv[i].x * w0;
                    acc[i][j] += xv[i].y * w1;
                    acc[i][j] += xv[i].z * w2;
                    acc[i][j] += xv[i].w * w3;
                }
            }
        }
    }
}

__global__ __launch_bounds__(256, 1)
void winattn_kernel(const float* __restrict__ x,
                    const float* __restrict__ qkv_w,
                    const float* __restrict__ qkv_b,
                    const float* __restrict__ rbt,
                    const float* __restrict__ proj_w,
                    const float* __restrict__ proj_b,
                    float* __restrict__ out)
{
    extern __shared__ float sm[];
    const int tid  = threadIdx.x;
    const int b    = blockIdx.x;
    const int cg   = tid & 15;
    const int rg   = tid >> 4;
    const int lane = tid & 31;
    const int warp = tid >> 5;

    // ---- load x tile [66][256] into smem ----
    const float* xg = x + (size_t)b * NT * C;
    for (int idx = tid; idx < NT*C/4; idx += 256) {
        int n = (idx*4) / C;
        int k = (idx*4) % C;
        float4 v = *(const float4*)(xg + n*C + k);
        float* d = &sm[XS_OFF + n*XS_STRIDE + k];
        d[0] = v.x; d[1] = v.y; d[2] = v.z; d[3] = v.w;
    }
    // (gemm_tile's first internal __syncthreads covers the x-load barrier)

    // ---- per-head attention ----
    for (int h = 0; h < NH; h++) {
        float acc[5][6];
#pragma unroll
        for (int i = 0; i < 5; i++)
#pragma unroll
            for (int j = 0; j < 6; j++) acc[i][j] = 0.f;

        // q/k/v slices for this head: cols 0..31 = q, 32..63 = k, 64..95 = v
        gemm_tile(sm, XS_OFF, qkv_w, 0, h, 0, tid, acc);

        // epilogue: add bias, scale q, write q/k/v to smem
#pragma unroll
        for (int i = 0; i < 5; i++) {
            int r = rg + 16*i;
            if (r < NT) {
#pragma unroll
                for (int j = 0; j < 6; j++) {
                    int c = cg*6 + j;
                    int m = c >> 5, d = c & 31;
                    float v = acc[i][j] + qkv_b[(m << 8) + (h << 5) + d];
                    if      (m == 0) sm[QS_OFF + r*QS_STRIDE + d] = v * QK_SCALE;
                    else if (m == 1) sm[KS_OFF + r*QS_STRIDE + d] = v;
                    else             sm[VS_OFF + r*QS_STRIDE + d] = v;
                }
            }
        }
        __syncthreads();

        // scores: s[row][col] = q[row] . k[col] + rel_bias
        for (int idx = tid; idx < NT*NT; idx += 256) {
            int row = idx / NT, col = idx % NT;
            const float* qp = &sm[QS_OFF + row*QS_STRIDE];
            const float* kp = &sm[KS_OFF + col*QS_STRIDE];
            float s = 0.f;
#pragma unroll
            for (int k = 0; k < HD; k++) s += qp[k] * kp[k];
            if (row >= TOKN && col >= TOKN) {
                int i = row - TOKN, j = col - TOKN;
                int bi = (((i >> 3) - (j >> 3) + 7) * 15) + ((i & 7) - (j & 7) + 7);
                s += rbt[bi * NH + h];
            }
            sm[SS_OFF + row*SS_STRIDE + col] = s;
        }
        __syncthreads();

        // softmax over each row (one warp per row, rows strided by 8)
        for (int row = warp; row < NT; row += 8) {
            float* sp = &sm[SS_OFF + row*SS_STRIDE];
            float v0 = sp[lane];
            float v1 = sp[lane + 32];
            float v2 = (lane < NT - 64) ? sp[lane + 64] : -INFINITY;
            float mx = fmaxf(fmaxf(v0, v1), v2);
#pragma unroll
            for (int o = 16; o > 0; o >>= 1)
                mx = fmaxf(mx, __shfl_xor_sync(0xffffffffu, mx, o));
            float e0 = __expf(v0 - mx);
            float e1 = __expf(v1 - mx);
            float e2 = (lane < NT - 64) ? __expf(v2 - mx) : 0.f;
            float s = e0 + e1 + e2;
#pragma unroll
            for (int o = 16; o > 0; o >>= 1)
                s += __shfl_xor_sync(0xffffffffu, s, o);
            float inv = 1.f / s;
            sp[lane]      = e0 * inv;
            sp[lane + 32] = e1 * inv;
            if (lane < NT - 64) sp[lane + 64] = e2 * inv;
        }
        __syncthreads();

        // o_h = P @ V  (thread: d = lane, rows g+8i), write into os head slice
        {
            const int d = tid & 31;
            const int g = tid >> 5;
            float oacc[9];
#pragma unroll
            for (int i = 0; i < 9; i++) oacc[i] = 0.f;
            for (int k = 0; k < NT; k++) {
                float vv = sm[VS_OFF + k*QS_STRIDE + d];
#pragma unroll
                for (int i = 0; i < 9; i++) {
                    int r = g + 8*i;
                    if (r < NT)
                        oacc[i] += sm[SS_OFF + r*SS_STRIDE + k] * vv;
                }
            }
#pragma unroll
            for (int i = 0; i < 9; i++) {
                int r = g + 8*i;
                if (r < NT)
                    sm[OS_OFF + r*XS_STRIDE + (h << 5) + d] = oacc[i];
            }
        }
        // next-head staging begins with __syncthreads inside gemm_tile
    }

    __syncthreads();

    // ---- output projection: out = os @ proj_w^T + proj_b ----
    float* og = out + (size_t)b * NT * C;
    for (int t = 0; t < 3; t++) {
        float acc[5][6];
#pragma unroll
        for (int i = 0; i < 5; i++)
#pragma unroll
            for (int j = 0; j < 6; j++) acc[i][j] = 0.f;

        gemm_tile(sm, OS_OFF, proj_w, 1, 0, 96*t, tid, acc);

#pragma unroll
        for (int i = 0; i < 5; i++) {
            int r = rg + 16*i;
            if (r < NT) {
#pragma unroll
                for (int j = 0; j < 6; j++) {
                    int c = 96*t + cg*6 + j;
                    if (c < C)
                        og[r*C + c] = acc[i][j] + proj_b[c];
                }
            }
        }
        // loop-head sync inside gemm_tile protects ws reuse
    }
}

extern "C" void kernel_launch(void* const* d_in, const int* in_sizes, int n_in,
                              void* d_out, int out_size) {
    const float* x      = (const float*)d_in[0];
    const float* qkv_w  = (const float*)d_in[1];
    const float* qkv_b  = (const float*)d_in[2];
    const float* rbt    = (const float*)d_in[3];
    const float* proj_w = (const float*)d_in[4];
    const float* proj_b = (const float*)d_in[5];
    float* out = (float*)d_out;

    size_t smem = (size_t)SM_TOTAL * sizeof(float);   // 206064 B
    cudaFuncSetAttribute(winattn_kernel,
                         cudaFuncAttributeMaxDynamicSharedMemorySize, (int)smem);
    winattn_kernel<<<NWIN, 256, smem>>>(x, qkv_w, qkv_b, rbt, proj_w, proj_b, out);
}

// round 3
// speedup vs baseline: 1.0003x; 1.0003x over previous
#include <cuda_runtime.h>
#include <math.h>

#define NWIN 2048
#define NT   66
#define C    256
#define NH   8
#define HD   32
#define TOKN 2
#define QK_SCALE 0.17677669529663687f   // 1/sqrt(32)

// shared memory layout (floats)
#define XS_STRIDE 260
#define QS_STRIDE 33
#define SS_STRIDE 67
#define WS_STRIDE 65

#define XS_OFF 0
#define OS_OFF (XS_OFF + NT*XS_STRIDE)          // 17160
#define WS_OFF (OS_OFF + NT*XS_STRIDE)          // 34320
#define QS_OFF (WS_OFF + 96*WS_STRIDE)          // 40560
#define KS_OFF (QS_OFF + NT*QS_STRIDE)          // 42738
#define VS_OFF (KS_OFF + NT*QS_STRIDE)          // 44916
#define SS_OFF (VS_OFF + NT*QS_STRIDE)          // 47094
#define SM_TOTAL (SS_OFF + NT*SS_STRIDE)        // 51516 floats = 206064 B

// Tiled GEMM: out[r][c] += sum_k xsrc[r][k] * Wg[grow(c)][k]
// 16x16 thread grid: thread owns up to 5 rows (rg+16i) x 6 cols (cg*6+j).
// mode 0: QKV slice for head h  -> grow = (c/32)*256 + h*32 + (c%32)
// mode 1: proj tile             -> grow = colbase + c   (guarded < 256)
__device__ __forceinline__ void gemm_tile(
    float* sm, int xoff, const float* __restrict__ Wg,
    int mode, int h, int colbase, int tid, float acc[5][6])
{
    const int cg = tid & 15;
    const int rg = tid >> 4;
    int roff[5];
#pragma unroll
    for (int i = 0; i < 5; i++) roff[i] = xoff + (rg + 16*i)*XS_STRIDE;

    for (int k0 = 0; k0 < C; k0 += 64) {
        __syncthreads();
        // stage W chunk [96 cols][64 k] into smem (float4 global reads)
        for (int idx = tid; idx < 96*16; idx += 256) {
            int c  = idx >> 4;
            int k4 = (idx & 15) * 4;
            int grow;
            if (mode == 0) grow = ((c >> 5) << 8) + (h << 5) + (c & 31);
            else           grow = colbase + c;
            if (mode == 0 || grow < C) {
                float4 w4 = *(const float4*)(Wg + (size_t)grow*C + k0 + k4);
                float* d = &sm[WS_OFF + c*WS_STRIDE + k4];
                d[0] = w4.x; d[1] = w4.y; d[2] = w4.z; d[3] = w4.w;
            }
        }
        __syncthreads();
        // accumulate
        const float* wsb = &sm[WS_OFF + (cg*6)*WS_STRIDE];
#pragma unroll 4
        for (int kk = 0; kk < 64; kk += 4) {
            float4 xv[5];
#pragma unroll
            for (int i = 0; i < 5; i++)
                xv[i] = *(const float4*)&sm[roff[i] + k0 + kk];
#pragma unroll
            for (int j = 0; j < 6; j++) {
                const float* wp = wsb + j*WS_STRIDE + kk;
                float w0 = wp[0], w1 = wp[1], w2 = wp[2], w3 = wp[3];
#pragma unroll
                for (int i = 0; i < 5; i++) {
                    acc[i][j] += xv[i].x * w0;
                    acc[i][j] += xv[i].y * w1;
                    acc[i][j] += xv[i].z * w2;
                    acc[i][j] += xv[i].w * w3;
                }
            }
        }
    }
}

__global__ __launch_bounds__(256, 1)
void winattn_kernel(const float* __restrict__ x,
                    const float* __restrict__ qkv_w,
                    const float* __restrict__ qkv_b,
                    const float* __restrict__ rbt,
                    const float* __restrict__ proj_w,
                    const float* __restrict__ proj_b,
                    float* __restrict__ out)
{
    extern __shared__ float sm[];
    const int tid  = threadIdx.x;
    const int b    = blockIdx.x;
    const int cg   = tid & 15;
    const int rg   = tid >> 4;
    const int lane = tid & 31;
    const int warp = tid >> 5;

    // ---- load x tile [66][256] into smem ----
    const float* xg = x + (size_t)b * NT * C;
    for (int idx = tid; idx < NT*C/4; idx += 256) {
        int n = (idx*4) / C;
        int k = (idx*4) % C;
        float4 v = *(const float4*)(xg + n*C + k);
        float* d = &sm[XS_OFF + n*XS_STRIDE + k];
        d[0] = v.x; d[1] = v.y; d[2] = v.z; d[3] = v.w;
    }
    // (gemm_tile's first internal __syncthreads covers the x-load barrier)

    // ---- per-head attention ----
    for (int h = 0; h < NH; h++) {
        float acc[5][6];
#pragma unroll
        for (int i = 0; i < 5; i++)
#pragma unroll
            for (int j = 0; j < 6; j++) acc[i][j] = 0.f;

        // q/k/v slices for this head: cols 0..31 = q, 32..63 = k, 64..95 = v
        gemm_tile(sm, XS_OFF, qkv_w, 0, h, 0, tid, acc);

        // epilogue: add bias, scale q, write q/k/v to smem
#pragma unroll
        for (int i = 0; i < 5; i++) {
            int r = rg + 16*i;
            if (r < NT) {
#pragma unroll
                for (int j = 0; j < 6; j++) {
                    int c = cg*6 + j;
                    int m = c >> 5, d = c & 31;
                    float v = acc[i][j] + qkv_b[(m << 8) + (h << 5) + d];
                    if      (m == 0) sm[QS_OFF + r*QS_STRIDE + d] = v * QK_SCALE;
                    else if (m == 1) sm[KS_OFF + r*QS_STRIDE + d] = v;
                    else             sm[VS_OFF + r*QS_STRIDE + d] = v;
                }
            }
        }
        __syncthreads();

        // scores: s[row][col] = q[row] . k[col] + rel_bias
        for (int idx = tid; idx < NT*NT; idx += 256) {
            int row = idx / NT, col = idx % NT;
            const float* qp = &sm[QS_OFF + row*QS_STRIDE];
            const float* kp = &sm[KS_OFF + col*QS_STRIDE];
            float s = 0.f;
#pragma unroll
            for (int k = 0; k < HD; k++) s += qp[k] * kp[k];
            if (row >= TOKN && col >= TOKN) {
                int i = row - TOKN, j = col - TOKN;
                int bi = (((i >> 3) - (j >> 3) + 7) * 15) + ((i & 7) - (j & 7) + 7);
                s += rbt[bi * NH + h];
            }
            sm[SS_OFF + row*SS_STRIDE + col] = s;
        }
        __syncthreads();

        // softmax over each row (one warp per row, rows strided by 8)
        for (int row = warp; row < NT; row += 8) {
            float* sp = &sm[SS_OFF + row*SS_STRIDE];
            float v0 = sp[lane];
            float v1 = sp[lane + 32];
            float v2 = (lane < NT - 64) ? sp[lane + 64] : -INFINITY;
            float mx = fmaxf(fmaxf(v0, v1), v2);
#pragma unroll
            for (int o = 16; o > 0; o >>= 1)
                mx = fmaxf(mx, __shfl_xor_sync(0xffffffffu, mx, o));
            float e0 = __expf(v0 - mx);
            float e1 = __expf(v1 - mx);
            float e2 = (lane < NT - 64) ? __expf(v2 - mx) : 0.f;
            float s = e0 + e1 + e2;
#pragma unroll
            for (int o = 16; o > 0; o >>= 1)
                s += __shfl_xor_sync(0xffffffffu, s, o);
            float inv = 1.f / s;
            sp[lane]      = e0 * inv;
            sp[lane + 32] = e1 * inv;
            if (lane < NT - 64) sp[lane + 64] = e2 * inv;
        }
        __syncthreads();

        // o_h = P @ V  (thread: d = lane, rows g+8i), write into os head slice
        {
            const int d = tid & 31;
            const int g = tid >> 5;
            float oacc[9];
#pragma unroll
            for (int i = 0; i < 9; i++) oacc[i] = 0.f;
            for (int k = 0; k < NT; k++) {
                float vv = sm[VS_OFF + k*QS_STRIDE + d];
#pragma unroll
                for (int i = 0; i < 9; i++) {
                    int r = g + 8*i;
                    if (r < NT)
                        oacc[i] += sm[SS_OFF + r*SS_STRIDE + k] * vv;
                }
            }
#pragma unroll
            for (int i = 0; i < 9; i++) {
                int r = g + 8*i;
                if (r < NT)
                    sm[OS_OFF + r*XS_STRIDE + (h << 5) + d] = oacc[i];
            }
        }
        // next-head staging begins with __syncthreads inside gemm_tile
    }

    __syncthreads();

    // ---- output projection: out = os @ proj_w^T + proj_b ----
    float* og = out + (size_t)b * NT * C;
    for (int t = 0; t < 3; t++) {
        float acc[5][6];
#pragma unroll
        for (int i = 0; i < 5; i++)
#pragma unroll
            for (int j = 0; j < 6; j++) acc[i][j] = 0.f;

        gemm_tile(sm, OS_OFF, proj_w, 1, 0, 96*t, tid, acc);

#pragma unroll
        for (int i = 0; i < 5; i++) {
            int r = rg + 16*i;
            if (r < NT) {
#pragma unroll
                for (int j = 0; j < 6; j++) {
                    int c = 96*t + cg*6 + j;
                    if (c < C)
                        og[r*C + c] = acc[i][j] + proj_b[c];
                }
            }
        }
        // loop-head sync inside gemm_tile protects ws reuse
    }
}

extern "C" void kernel_launch(void* const* d_in, const int* in_sizes, int n_in,
                              void* d_out, int out_size) {
    const float* x      = (const float*)d_in[0];
    const float* qkv_w  = (const float*)d_in[1];
    const float* qkv_b  = (const float*)d_in[2];
    const float* rbt    = (const float*)d_in[3];
    const float* proj_w = (const float*)d_in[4];
    const float* proj_b = (const float*)d_in[5];
    float* out = (float*)d_out;

    size_t smem = (size_t)SM_TOTAL * sizeof(float);   // 206064 B
    cudaFuncSetAttribute(winattn_kernel,
                         cudaFuncAttributeMaxDynamicSharedMemorySize, (int)smem);
    winattn_kernel<<<NWIN, 256, smem>>>(x, qkv_w, qkv_b, rbt, proj_w, proj_b, out);
}